// round 1
// baseline (speedup 1.0000x reference)
#include <cuda_runtime.h>

// Problem constants (from reference): B=2048 derived at launch, C=16, D=256, W=3
#define W        3
#define CND      16
#define DIM      256
#define PITCH    260          // floats per smem tile row (pad to limit bank conflicts)
#define CPB      4            // batches per block
#define NT       (CPB + 2*W)  // 10 staged batch tiles
#define NTHREADS 256
#define THRED    0.8f
#define EPSV     1e-8f
#define OUTC     (DIM + 6*CND + 1)   // 353

__global__ __launch_bounds__(NTHREADS, 1)
void graph_build_kernel(const float* __restrict__ cand,
                        const int*   __restrict__ nm,
                        float*       __restrict__ out,
                        int B) {
    extern __shared__ float sm[];
    float* tiles = sm;                            // NT*CND*PITCH
    float* nrm   = tiles + NT * CND * PITCH;      // NT*CND
    float* rmask = nrm   + NT * CND;              // NT*CND
    float* mprod = rmask + NT * CND;              // CPB*6*CND

    const int tid = threadIdx.x;
    const int b0  = blockIdx.x * CPB;

    // ---- Phase A: stage 10 batch tiles (b0-3 .. b0+6), zero-fill out of range ----
    const int NF4 = NT * CND * (DIM / 4);   // 10240 float4
    for (int idx = tid; idx < NF4; idx += NTHREADS) {
        int t   = idx / (CND * (DIM / 4));
        int rem = idx - t * (CND * (DIM / 4));
        int r   = rem / (DIM / 4);
        int d4  = rem - r * (DIM / 4);
        int bb  = b0 - W + t;
        float4 v = make_float4(0.f, 0.f, 0.f, 0.f);
        if (bb >= 0 && bb < B)
            v = *(const float4*)(cand + ((size_t)(bb * CND + r)) * DIM + d4 * 4);
        *(float4*)(tiles + (t * CND + r) * PITCH + d4 * 4) = v;
    }
    // masks per staged batch (0 out of range)
    for (int idx = tid; idx < NT * CND; idx += NTHREADS) {
        int bb = b0 - W + idx / CND;
        int c  = idx - (idx / CND) * CND;
        rmask[idx] = (bb >= 0 && bb < B) ? (float)nm[bb * CND + c] : 0.f;
    }
    __syncthreads();

    // ---- Phase B: row norms + cumulative shift-mask products ----
    for (int idx = tid; idx < NT * CND; idx += NTHREADS) {
        const float4* row = (const float4*)(tiles + idx * PITCH);
        float s = 0.f;
        #pragma unroll 8
        for (int d4 = 0; d4 < DIM / 4; d4++) {
            float4 v = row[d4];
            s += v.x * v.x + v.y * v.y + v.z * v.z + v.w * v.w;
        }
        nrm[idx] = sqrtf(s);
    }
    for (int idx = tid; idx < CPB * 6 * CND; idx += NTHREADS) {
        int g   = idx / (6 * CND);
        int rem = idx - g * 6 * CND;
        int p   = rem / CND;
        int c   = rem - p * CND;
        int bt  = b0 + g;
        float m = 0.f;
        if (bt < B) {
            if (p < W) {                       // left shift k = p+1: prod rmask[bt-1..bt-k]
                int k = p + 1;
                if (bt - k >= 0) {
                    m = 1.f;
                    for (int jj = 1; jj <= k; jj++) m *= rmask[(W + g - jj) * CND + c];
                }
            } else {                           // right shift k = p-2: prod rmask[bt..bt+k-1]
                int k = p - W + 1;
                if (bt + k < B) {
                    m = 1.f;
                    for (int jj = 0; jj < k; jj++) m *= rmask[(W + g + jj) * CND + c];
                }
            }
        }
        mprod[idx] = m;
    }
    __syncthreads();

    // ---- Phase C: grams + adjacency rows ----
    const int i = tid >> 4;      // candidate row 0..15
    const int j = tid & 15;      // candidate col 0..15

    for (int g = 0; g < CPB; g++) {
        int bt = b0 + g;
        if (bt >= B) break;
        const float4* S  = (const float4*)(tiles + ((W + g) * CND + i) * PITCH);
        const float4* T0 = (const float4*)(tiles + ((W + g - 1) * CND + j) * PITCH);
        const float4* T1 = (const float4*)(tiles + ((W + g - 2) * CND + j) * PITCH);
        const float4* T2 = (const float4*)(tiles + ((W + g - 3) * CND + j) * PITCH);
        const float4* T3 = (const float4*)(tiles + ((W + g + 1) * CND + j) * PITCH);
        const float4* T4 = (const float4*)(tiles + ((W + g + 2) * CND + j) * PITCH);
        const float4* T5 = (const float4*)(tiles + ((W + g + 3) * CND + j) * PITCH);

        float a0 = 0.f, a1 = 0.f, a2 = 0.f, a3 = 0.f, a4 = 0.f, a5 = 0.f;
        #pragma unroll 8
        for (int d4 = 0; d4 < DIM / 4; d4++) {
            float4 s = S[d4];
            float4 t;
            t = T0[d4]; a0 += s.x * t.x + s.y * t.y + s.z * t.z + s.w * t.w;
            t = T1[d4]; a1 += s.x * t.x + s.y * t.y + s.z * t.z + s.w * t.w;
            t = T2[d4]; a2 += s.x * t.x + s.y * t.y + s.z * t.z + s.w * t.w;
            t = T3[d4]; a3 += s.x * t.x + s.y * t.y + s.z * t.z + s.w * t.w;
            t = T4[d4]; a4 += s.x * t.x + s.y * t.y + s.z * t.z + s.w * t.w;
            t = T5[d4]; a5 += s.x * t.x + s.y * t.y + s.z * t.z + s.w * t.w;
        }

        float nc = nrm[(W + g) * CND + i];
        float accs[6] = {a0, a1, a2, a3, a4, a5};
        float vals[6];
        float rs = 0.f;
        #pragma unroll
        for (int p = 0; p < 6; p++) {
            int dlt   = (p < W) ? -(p + 1) : (p - W + 1);
            float nj  = nrm[(W + g + dlt) * CND + j];
            float v   = accs[p] / fmaxf(nc * nj, EPSV);
            float m   = mprod[(g * 6 + p) * CND + j];
            float a   = (m != 0.f && v > THRED) ? fminf(v, 1.f) : 0.f;
            vals[p]   = a;
            rs       += a;
        }
        // L1 row sum across the 16 threads sharing i (lane groups of 16 are aligned)
        #pragma unroll
        for (int o = 1; o < 16; o <<= 1) rs += __shfl_xor_sync(0xffffffffu, rs, o);
        float inv = 1.f / fmaxf(rs + 1.f, 1e-12f);   // RHO=1, +1 for ones column

        size_t base = ((size_t)bt * CND + i) * OUTC;
        #pragma unroll
        for (int p = 0; p < 6; p++)
            out[base + DIM + p * CND + j] = vals[p] * inv;
        if (j == 0)
            out[base + DIM + 6 * CND] = inv;
    }

    // ---- Phase D: neighbor-mean embeddings (256 threads cover one row's dims) ----
    for (int r = 0; r < CPB * CND; r++) {
        int g = r >> 4;
        int c = r & 15;
        if (b0 + g >= B) break;
        float acc = 0.f;
        #pragma unroll
        for (int p = 0; p < 6; p++) {
            int dlt  = (p < W) ? -(p + 1) : (p - W + 1);
            float m  = mprod[(g * 6 + p) * CND + c];
            acc     += m * tiles[((W + g + dlt) * CND + c) * PITCH + tid];
        }
        out[((size_t)(b0 + g) * CND + c) * OUTC + tid] = acc * (1.f / 6.f);
    }
}

extern "C" void kernel_launch(void* const* d_in, const int* in_sizes, int n_in,
                              void* d_out, int out_size) {
    const float* cand = (const float*)d_in[0];
    const int*   nm   = (const int*)d_in[1];
    float*       out  = (float*)d_out;
    int B = in_sizes[1] / CND;   // 2048

    int smem_bytes = (NT * CND * PITCH + 2 * NT * CND + CPB * 6 * CND) * (int)sizeof(float);
    cudaFuncSetAttribute(graph_build_kernel,
                         cudaFuncAttributeMaxDynamicSharedMemorySize, smem_bytes);

    int grid = (B + CPB - 1) / CPB;  // 512
    graph_build_kernel<<<grid, NTHREADS, smem_bytes>>>(cand, nm, out, B);
}

// round 7
// speedup vs baseline: 1.9088x; 1.9088x over previous
#include <cuda_runtime.h>

// B=2048 (derived at launch), C=16, D=256, W=3
#define W        3
#define CND      16
#define DIM      256
#define PITCH    260           // floats per smem row; 4·r mod 32 distinct over 8 consecutive rows
#define P4       65            // PITCH/4, float4 per row (16B aligned: 260*4=1040)
#define CPB      7             // batches per block
#define NT       (CPB + 2*W)   // 13 staged batch tiles
#define NTHREADS 512
#define THRED    0.8f
#define EPSV     1e-8f
#define OUTC     (DIM + 6*CND + 1)   // 353

__global__ __launch_bounds__(NTHREADS, 1)
void graph_build_kernel(const float* __restrict__ cand,
                        const int*   __restrict__ nm,
                        float*       __restrict__ out,
                        int B) {
    extern __shared__ float sm[];
    float* tiles = sm;                            // NT*CND*PITCH floats
    float* nrm   = tiles + NT * CND * PITCH;      // NT*CND
    float* rmask = nrm   + NT * CND;              // NT*CND
    float* mprod = rmask + NT * CND;              // CPB*6*CND
    float4* t4   = (float4*)tiles;

    const int tid  = threadIdx.x;
    const int b0   = blockIdx.x * CPB;
    const int wid  = tid >> 5;
    const int lane = tid & 31;

    // ---- Phase A: stage 13 batch tiles (b0-3 .. b0+9), zero-fill out of range ----
    const int NF4 = NT * CND * (DIM / 4);   // 13312
    for (int idx = tid; idx < NF4; idx += NTHREADS) {
        int t   = idx / (CND * (DIM / 4));
        int rem = idx - t * (CND * (DIM / 4));
        int r   = rem >> 6;
        int k4  = rem & 63;
        int bb  = b0 - W + t;
        float4 v = make_float4(0.f, 0.f, 0.f, 0.f);
        if (bb >= 0 && bb < B)
            v = *(const float4*)(cand + ((size_t)(bb * CND + r)) * DIM + k4 * 4);
        t4[(t * CND + r) * P4 + k4] = v;
    }
    for (int idx = tid; idx < NT * CND; idx += NTHREADS) {
        int bb = b0 - W + idx / CND;
        int c  = idx & 15;
        rmask[idx] = (bb >= 0 && bb < B) ? (float)nm[bb * CND + c] : 0.f;
    }
    __syncthreads();

    // ---- Phase B: row norms (one warp per row) + shift-mask products ----
    for (int row = wid; row < NT * CND; row += (NTHREADS / 32)) {
        float4 a = t4[row * P4 + lane];
        float4 b = t4[row * P4 + 32 + lane];
        float s = a.x*a.x + a.y*a.y + a.z*a.z + a.w*a.w
                + b.x*b.x + b.y*b.y + b.z*b.z + b.w*b.w;
        #pragma unroll
        for (int o = 16; o >= 1; o >>= 1) s += __shfl_xor_sync(0xffffffffu, s, o);
        if (lane == 0) nrm[row] = sqrtf(s);
    }
    for (int idx = tid; idx < CPB * 6 * CND; idx += NTHREADS) {
        int g   = idx / (6 * CND);
        int rem = idx - g * 6 * CND;
        int p   = rem / CND;
        int c   = rem - p * CND;
        int bt  = b0 + g;
        float m = 0.f;
        if (bt < B) {
            if (p < W) {                       // left shift k = p+1: prod nm[bt-1..bt-k]
                int k = p + 1;
                if (bt - k >= 0) {
                    m = 1.f;
                    for (int jj = 1; jj <= k; jj++) m *= rmask[(W + g - jj) * CND + c];
                }
            } else {                           // right shift k = p-2: prod nm[bt..bt+k-1]
                int k = p - W + 1;
                if (bt + k < B) {
                    m = 1.f;
                    for (int jj = 0; jj < k; jj++) m *= rmask[(W + g + jj) * CND + c];
                }
            }
        }
        mprod[idx] = m;
    }
    __syncthreads();

    // ---- Phase C: register-tiled grams (2 warps per batch, 2x2 output tile/thread) ----
    if (wid < 2 * CPB) {
        const int g    = wid >> 1;
        const int half = wid & 1;
        const int bt   = b0 + g;
        if (bt < B) {
            const int i2 = half * 4 + (lane >> 3);   // 0..7
            const int j2 = lane & 7;                 // 0..7

            const float4* A0 = t4 + ((W + g) * CND + i2) * P4;
            const float4* A1 = A0 + 8 * P4;
            const float4* Tp0 = t4 + ((W + g - 1) * CND + j2) * P4;
            const float4* Tp1 = t4 + ((W + g - 2) * CND + j2) * P4;
            const float4* Tp2 = t4 + ((W + g - 3) * CND + j2) * P4;
            const float4* Tp3 = t4 + ((W + g + 1) * CND + j2) * P4;
            const float4* Tp4 = t4 + ((W + g + 2) * CND + j2) * P4;
            const float4* Tp5 = t4 + ((W + g + 3) * CND + j2) * P4;

            float acc[6][4];
            #pragma unroll
            for (int p = 0; p < 6; p++)
                #pragma unroll
                for (int q = 0; q < 4; q++) acc[p][q] = 0.f;

            #pragma unroll 8
            for (int k4 = 0; k4 < 64; k4++) {
                float4 s0 = A0[k4];
                float4 s1 = A1[k4];
                #pragma unroll
                for (int p = 0; p < 6; p++) {
                    const float4* Tb = (p == 0) ? Tp0 : (p == 1) ? Tp1 : (p == 2) ? Tp2
                                     : (p == 3) ? Tp3 : (p == 4) ? Tp4 : Tp5;
                    float4 u = Tb[k4];
                    float4 v = Tb[8 * P4 + k4];
                    acc[p][0] += s0.x*u.x + s0.y*u.y + s0.z*u.z + s0.w*u.w;
                    acc[p][1] += s0.x*v.x + s0.y*v.y + s0.z*v.z + s0.w*v.w;
                    acc[p][2] += s1.x*u.x + s1.y*u.y + s1.z*u.z + s1.w*u.w;
                    acc[p][3] += s1.x*v.x + s1.y*v.y + s1.z*v.z + s1.w*v.w;
                }
            }

            const float nc0 = nrm[(W + g) * CND + i2];
            const float nc1 = nrm[(W + g) * CND + i2 + 8];
            float vals[6][4];
            float rs0 = 0.f, rs1 = 0.f;
            #pragma unroll
            for (int p = 0; p < 6; p++) {
                int dlt  = (p < W) ? -(p + 1) : (p - W + 1);
                float nj0 = nrm[(W + g + dlt) * CND + j2];
                float nj1 = nrm[(W + g + dlt) * CND + j2 + 8];
                float m0  = mprod[(g * 6 + p) * CND + j2];
                float m1  = mprod[(g * 6 + p) * CND + j2 + 8];
                float v00 = __fdividef(acc[p][0], fmaxf(nc0 * nj0, EPSV));
                float v01 = __fdividef(acc[p][1], fmaxf(nc0 * nj1, EPSV));
                float v10 = __fdividef(acc[p][2], fmaxf(nc1 * nj0, EPSV));
                float v11 = __fdividef(acc[p][3], fmaxf(nc1 * nj1, EPSV));
                vals[p][0] = (m0 != 0.f && v00 > THRED) ? fminf(v00, 1.f) : 0.f;
                vals[p][1] = (m1 != 0.f && v01 > THRED) ? fminf(v01, 1.f) : 0.f;
                vals[p][2] = (m0 != 0.f && v10 > THRED) ? fminf(v10, 1.f) : 0.f;
                vals[p][3] = (m1 != 0.f && v11 > THRED) ? fminf(v11, 1.f) : 0.f;
                rs0 += vals[p][0] + vals[p][1];
                rs1 += vals[p][2] + vals[p][3];
            }
            // L1 row sums across the 8-lane group sharing i2
            #pragma unroll
            for (int o = 1; o < 8; o <<= 1) {
                rs0 += __shfl_xor_sync(0xffffffffu, rs0, o);
                rs1 += __shfl_xor_sync(0xffffffffu, rs1, o);
            }
            const float inv0 = __fdividef(1.f, fmaxf(rs0 + 1.f, 1e-12f));
            const float inv1 = __fdividef(1.f, fmaxf(rs1 + 1.f, 1e-12f));

            const size_t base0 = ((size_t)bt * CND + i2) * OUTC + DIM;
            const size_t base1 = ((size_t)bt * CND + i2 + 8) * OUTC + DIM;
            #pragma unroll
            for (int p = 0; p < 6; p++) {
                out[base0 + p * CND + j2]     = vals[p][0] * inv0;
                out[base0 + p * CND + j2 + 8] = vals[p][1] * inv0;
                out[base1 + p * CND + j2]     = vals[p][2] * inv1;
                out[base1 + p * CND + j2 + 8] = vals[p][3] * inv1;
            }
            if (j2 == 0) {
                out[base0 + 6 * CND] = inv0;
                out[base1 + 6 * CND] = inv1;
            }
        }
    }

    // ---- Phase D: neighbor-mean embeddings (2 rows in flight across 512 threads) ----
    {
        const int dh = tid >> 8;     // which row of the pair
        const int d  = tid & 255;    // embedding dim
        for (int rr = dh; rr < CPB * CND; rr += 2) {
            int g = rr >> 4;
            int c = rr & 15;
            int bt = b0 + g;
            if (bt >= B) continue;
            float a = 0.f;
            #pragma unroll
            for (int p = 0; p < 6; p++) {
                int dlt = (p < W) ? -(p + 1) : (p - W + 1);
                a += mprod[(g * 6 + p) * CND + c]
                   * tiles[((W + g + dlt) * CND + c) * PITCH + d];
            }
            out[((size_t)bt * CND + c) * OUTC + d] = a * (1.f / 6.f);
        }
    }
}

extern "C" void kernel_launch(void* const* d_in, const int* in_sizes, int n_in,
                              void* d_out, int out_size) {
    const float* cand = (const float*)d_in[0];
    const int*   nm   = (const int*)d_in[1];
    float*       out  = (float*)d_out;
    int B = in_sizes[1] / CND;   // 2048

    int smem_bytes = (NT * CND * PITCH + 2 * NT * CND + CPB * 6 * CND) * (int)sizeof(float);
    cudaFuncSetAttribute(graph_build_kernel,
                         cudaFuncAttributeMaxDynamicSharedMemorySize, smem_bytes);

    int grid = (B + CPB - 1) / CPB;  // 293
    graph_build_kernel<<<grid, NTHREADS, smem_bytes>>>(cand, nm, out, B);
}